// round 1
// baseline (speedup 1.0000x reference)
#include <cuda_runtime.h>

#define DMODEL 512
#define SEQ_T 2048
#define BATCH 4
#define NHEAD 8
#define HD 64
#define QKV_N (3 * DMODEL)

// Scratch (allocation-free rule: __device__ globals)
__device__ float g_qkv[(size_t)BATCH * SEQ_T * QKV_N];   // [B, T, 3*D]
__device__ float g_att[(size_t)BATCH * SEQ_T * DMODEL];  // [B, T, D]

// ---------------------------------------------------------------------------
// SGEMM: C[M,N] = A[M,K] @ B[K,N] + bias[N]
// 128x128 block tile, KT=8, 256 threads, 8x8 micro-tile per thread
// (split as 2x 4-row halves / 2x 4-col halves for conflict-free smem reads)
// Assumes M%128==0, N%128==0, K%8==0 (true for all launches here).
// ---------------------------------------------------------------------------
__global__ __launch_bounds__(256) void sgemm_bias(
    const float* __restrict__ A, const float* __restrict__ Bm,
    const float* __restrict__ bias, float* __restrict__ C,
    int M, int N, int K)
{
    __shared__ float As[8][128];
    __shared__ float Bs[8][128];

    const int tid = threadIdx.x;
    const int bm = blockIdx.y * 128;
    const int bn = blockIdx.x * 128;
    const int tx = tid & 15;   // 0..15
    const int ty = tid >> 4;   // 0..15

    float acc[8][8];
#pragma unroll
    for (int i = 0; i < 8; i++)
#pragma unroll
        for (int j = 0; j < 8; j++) acc[i][j] = 0.f;

    // global load mapping
    const int a_row = tid >> 1;          // 0..127
    const int a_col = (tid & 1) * 4;     // 0 or 4
    const int b_row = tid >> 5;          // 0..7
    const int b_col = (tid & 31) * 4;    // 0..124

    const float* Ap = A + (size_t)(bm + a_row) * K + a_col;
    const float* Bp = Bm + (size_t)b_row * N + bn + b_col;

    for (int k0 = 0; k0 < K; k0 += 8) {
        float4 av = *(const float4*)(Ap + k0);
        float4 bv = *(const float4*)(Bp + (size_t)k0 * N);
        __syncthreads();
        As[a_col + 0][a_row] = av.x;
        As[a_col + 1][a_row] = av.y;
        As[a_col + 2][a_row] = av.z;
        As[a_col + 3][a_row] = av.w;
        *(float4*)&Bs[b_row][b_col] = bv;
        __syncthreads();

#pragma unroll
        for (int kk = 0; kk < 8; kk++) {
            float af[8], bf[8];
            *(float4*)(af)     = *(const float4*)&As[kk][ty * 4];
            *(float4*)(af + 4) = *(const float4*)&As[kk][64 + ty * 4];
            *(float4*)(bf)     = *(const float4*)&Bs[kk][tx * 4];
            *(float4*)(bf + 4) = *(const float4*)&Bs[kk][64 + tx * 4];
#pragma unroll
            for (int i = 0; i < 8; i++)
#pragma unroll
                for (int j = 0; j < 8; j++)
                    acc[i][j] += af[i] * bf[j];
        }
    }

    // epilogue: rows {ih*64 + ty*4 + i}, cols {jh*64 + tx*4 + j}
    float bl[8];
    *(float4*)(bl)     = *(const float4*)&bias[bn + tx * 4];
    *(float4*)(bl + 4) = *(const float4*)&bias[bn + 64 + tx * 4];
#pragma unroll
    for (int ih = 0; ih < 2; ih++) {
#pragma unroll
        for (int i = 0; i < 4; i++) {
            const int row = bm + ih * 64 + ty * 4 + i;
            float* crow = C + (size_t)row * N + bn;
#pragma unroll
            for (int jh = 0; jh < 2; jh++) {
                float4 o;
                o.x = acc[ih * 4 + i][jh * 4 + 0] + bl[jh * 4 + 0];
                o.y = acc[ih * 4 + i][jh * 4 + 1] + bl[jh * 4 + 1];
                o.z = acc[ih * 4 + i][jh * 4 + 2] + bl[jh * 4 + 2];
                o.w = acc[ih * 4 + i][jh * 4 + 3] + bl[jh * 4 + 3];
                *(float4*)(crow + jh * 64 + tx * 4) = o;
            }
        }
    }
}

// ---------------------------------------------------------------------------
// Causal flash attention, fp32.
// One thread = one query row. Block = 128 threads = 128 query rows.
// K/V tiles (64 keys x 64 dims) staged in shared memory per (b,h).
// Online softmax with rare-rescale (only when running max changes).
// grid = (T/128, B*H)
// ---------------------------------------------------------------------------
__global__ __launch_bounds__(128) void attn_kernel(
    const float* __restrict__ qkv, float* __restrict__ att)
{
    const int bh = blockIdx.y;
    const int b = bh >> 3;        // NHEAD=8
    const int h = bh & 7;
    const int q0 = blockIdx.x * 128;
    const int tid = threadIdx.x;
    const int qi = q0 + tid;

    const float* base = qkv + (size_t)b * SEQ_T * QKV_N;

    // load and pre-scale q row (1/sqrt(64) = 0.125)
    float4 q[16];
    {
        const float4* qp = (const float4*)(base + (size_t)qi * QKV_N + h * HD);
#pragma unroll
        for (int i = 0; i < 16; i++) {
            float4 t = qp[i];
            t.x *= 0.125f; t.y *= 0.125f; t.z *= 0.125f; t.w *= 0.125f;
            q[i] = t;
        }
    }

    float m = -1e30f, l = 0.f;
    float acc[64];
#pragma unroll
    for (int i = 0; i < 64; i++) acc[i] = 0.f;

    __shared__ float Ks[64][64];
    __shared__ float Vs[64][64];

    const int kv_end = q0 + 128;   // keys needed by this block (exclusive)

    for (int j0 = 0; j0 < kv_end; j0 += 64) {
        __syncthreads();
        // cooperative load of K/V tile: 64 rows x 64 floats each
#pragma unroll
        for (int i = 0; i < 8; i++) {
            const int idx = tid + i * 128;        // 0..1023
            const int r = idx >> 4;
            const int c = (idx & 15) << 2;
            const float* krow = base + (size_t)(j0 + r) * QKV_N + DMODEL + h * HD + c;
            *(float4*)&Ks[r][c] = *(const float4*)krow;
            *(float4*)&Vs[r][c] = *(const float4*)(krow + DMODEL);
        }
        __syncthreads();

        int jmax = qi - j0 + 1;
        if (jmax > 64) jmax = 64;
        for (int j = 0; j < jmax; j++) {
            const float4* kp = (const float4*)Ks[j];
            float s0 = 0.f, s1 = 0.f, s2 = 0.f, s3 = 0.f;
#pragma unroll
            for (int i = 0; i < 16; i += 4) {
                float4 k0 = kp[i], k1 = kp[i + 1], k2 = kp[i + 2], k3 = kp[i + 3];
                s0 += q[i].x * k0.x + q[i].y * k0.y + q[i].z * k0.z + q[i].w * k0.w;
                s1 += q[i + 1].x * k1.x + q[i + 1].y * k1.y + q[i + 1].z * k1.z + q[i + 1].w * k1.w;
                s2 += q[i + 2].x * k2.x + q[i + 2].y * k2.y + q[i + 2].z * k2.z + q[i + 2].w * k2.w;
                s3 += q[i + 3].x * k3.x + q[i + 3].y * k3.y + q[i + 3].z * k3.z + q[i + 3].w * k3.w;
            }
            const float s = (s0 + s1) + (s2 + s3);

            if (s > m) {   // rare: running max update + rescale
                const float corr = __expf(m - s);
                l *= corr;
#pragma unroll
                for (int d = 0; d < 64; d++) acc[d] *= corr;
                m = s;
            }
            const float p = __expf(s - m);
            l += p;

            const float4* vp = (const float4*)Vs[j];
#pragma unroll
            for (int i = 0; i < 16; i++) {
                float4 v = vp[i];
                acc[4 * i + 0] += p * v.x;
                acc[4 * i + 1] += p * v.y;
                acc[4 * i + 2] += p * v.z;
                acc[4 * i + 3] += p * v.w;
            }
        }
    }

    const float inv = 1.f / l;
    float* op = att + (size_t)(b * SEQ_T + qi) * DMODEL + h * HD;
#pragma unroll
    for (int i = 0; i < 16; i++) {
        float4 o;
        o.x = acc[4 * i + 0] * inv;
        o.y = acc[4 * i + 1] * inv;
        o.z = acc[4 * i + 2] * inv;
        o.w = acc[4 * i + 3] * inv;
        ((float4*)op)[i] = o;
    }
}

// ---------------------------------------------------------------------------
extern "C" void kernel_launch(void* const* d_in, const int* in_sizes, int n_in,
                              void* d_out, int out_size)
{
    (void)in_sizes; (void)n_in; (void)out_size;
    const float* x     = (const float*)d_in[0];
    const float* W_qkv = (const float*)d_in[1];
    const float* b_qkv = (const float*)d_in[2];
    const float* W_out = (const float*)d_in[3];
    const float* b_out = (const float*)d_in[4];
    float* out = (float*)d_out;

    float* qkvp = nullptr;
    float* attp = nullptr;
    cudaGetSymbolAddress((void**)&qkvp, g_qkv);
    cudaGetSymbolAddress((void**)&attp, g_att);

    const int M = BATCH * SEQ_T;   // 8192

    // 1) QKV projection: [8192,512] @ [512,1536] + b
    {
        dim3 grid(QKV_N / 128, M / 128);   // (12, 64)
        sgemm_bias<<<grid, 256>>>(x, W_qkv, b_qkv, qkvp, M, QKV_N, DMODEL);
    }
    // 2) causal flash attention
    {
        dim3 grid(SEQ_T / 128, BATCH * NHEAD);   // (16, 32)
        attn_kernel<<<grid, 128>>>(qkvp, attp);
    }
    // 3) output projection: [8192,512] @ [512,512] + b
    {
        dim3 grid(DMODEL / 128, M / 128);  // (4, 64)
        sgemm_bias<<<grid, 256>>>(attp, W_out, b_out, out, M, DMODEL, DMODEL);
    }
}